// round 2
// baseline (speedup 1.0000x reference)
#include <cuda_runtime.h>
#include <math.h>

#define NB    4096      // N boxes
#define NFG_  1024
#define NFP_  256
#define NFR_  256
#define NG_   4
#define FPPD  1280      // NFP + NFG
#define THR2  302.76f   // (0.2*87)^2
#define SIMSCALE 0.044194173824159216f  // 1/sqrt(512)

// ---------------- device scratch (static, allocation-free) ----------------
__device__ float g_foot[NB * 2];
__device__ float g_fpp [(size_t)NB * FPPD];                 // 20 MB
__device__ float g_theta[(size_t)NG_ * NB * NFR_];          // 16 MB
__device__ float g_phi  [(size_t)NG_ * NB * NFR_];          // 16 MB
__device__ float g_phiT [(size_t)NG_ * NFR_ * NB];          // 16 MB
__device__ float g_sim  [(size_t)NG_ * NB * NB];            // 256 MB (becomes A in-place)
__device__ float g_agg  [(size_t)NG_ * NB * NFG_];          // 64 MB
__device__ float g_outp [(size_t)NG_ * NB * NFG_];          // 64 MB

// ---------------- foot points ----------------
__global__ void foot_kernel(const float* __restrict__ boxes, float* __restrict__ foot) {
    int n = blockIdx.x * 256 + threadIdx.x;
    if (n < NB) {
        foot[2 * n]     = (boxes[4 * n + 0] + boxes[4 * n + 2]) * 0.5f;
        foot[2 * n + 1] = boxes[4 * n + 3];
    }
}

// ---------------- fpp = [sincos_emb(foot, 256) | feats] ----------------
__global__ void fpp_kernel(const float* __restrict__ feats,
                           const float* __restrict__ foot,
                           float* __restrict__ fpp) {
    long long idx = (long long)blockIdx.x * 256 + threadIdx.x;
    if (idx >= (long long)NB * FPPD) return;
    int n = (int)(idx / FPPD);
    int j = (int)(idx % FPPD);
    float v;
    if (j < NFP_) {
        int coord = j / 128;          // 0: x, 1: y
        int jj = j % 128;
        int i = jj & 63;              // frequency index
        bool is_cos = jj >= 64;
        // freq = 10000^(-i/64) = exp(-i * ln(10000)/64)
        float freq = expf(-(float)i * 0.14391157750382243f);
        float ang = foot[2 * n + coord] * freq;
        v = is_cos ? cosf(ang) : sinf(ang);
    } else {
        v = feats[(long long)n * NFG_ + (j - NFP_)];
    }
    fpp[idx] = v;
}

// ---------------- generic batched SGEMM (NN, row-major), 128x128x8 ----------------
// epi: 0 = +bias[col], 1 = scale + position-mask -> -inf, 2 = plain
#define BM 128
#define BN 128
#define BK 8
#define TM 8
#define TN 8

__global__ __launch_bounds__(256, 2)
void sgemm_kernel(const float* __restrict__ Aall, const float* __restrict__ Ball,
                  float* __restrict__ Call,
                  int M, int N, int K,
                  long long sA, long long sB, long long sC,
                  int epi,
                  const float* __restrict__ bias, int sBias,
                  const float* __restrict__ foot, float scale)
{
    int g = blockIdx.z;
    const float* A = Aall + (long long)g * sA;
    const float* B = Ball + (long long)g * sB;
    float*       C = Call + (long long)g * sC;

    __shared__ float As[BK][BM];
    __shared__ float Bs[BK][BN];

    int tid = threadIdx.x;
    int tx = tid & 15;         // 0..15
    int ty = tid >> 4;         // 0..15
    int rowBase = blockIdx.y * BM;
    int colBase = blockIdx.x * BN;

    int aRow = tid >> 1;           // 0..127
    int aCol = (tid & 1) * 4;      // 0 or 4
    int bRow = tid >> 5;           // 0..7
    int bCol = (tid & 31) * 4;     // 0..124

    float acc[TM][TN];
    #pragma unroll
    for (int i = 0; i < TM; i++)
        #pragma unroll
        for (int j = 0; j < TN; j++) acc[i][j] = 0.0f;

    const float* aPtr = A + (long long)(rowBase + aRow) * K + aCol;
    const float* bPtr = B + (long long)bRow * N + colBase + bCol;

    for (int k0 = 0; k0 < K; k0 += BK) {
        float4 av = *reinterpret_cast<const float4*>(aPtr + k0);
        As[aCol + 0][aRow] = av.x;
        As[aCol + 1][aRow] = av.y;
        As[aCol + 2][aRow] = av.z;
        As[aCol + 3][aRow] = av.w;
        float4 bv = *reinterpret_cast<const float4*>(bPtr + (long long)k0 * N);
        *reinterpret_cast<float4*>(&Bs[bRow][bCol]) = bv;
        __syncthreads();
        #pragma unroll
        for (int kk = 0; kk < BK; kk++) {
            float4 a0 = *reinterpret_cast<const float4*>(&As[kk][ty * TM]);
            float4 a1 = *reinterpret_cast<const float4*>(&As[kk][ty * TM + 4]);
            float4 b0 = *reinterpret_cast<const float4*>(&Bs[kk][tx * TN]);
            float4 b1 = *reinterpret_cast<const float4*>(&Bs[kk][tx * TN + 4]);
            float ra[TM] = {a0.x, a0.y, a0.z, a0.w, a1.x, a1.y, a1.z, a1.w};
            float rb[TN] = {b0.x, b0.y, b0.z, b0.w, b1.x, b1.y, b1.z, b1.w};
            #pragma unroll
            for (int i = 0; i < TM; i++)
                #pragma unroll
                for (int j = 0; j < TN; j++)
                    acc[i][j] += ra[i] * rb[j];
        }
        __syncthreads();
    }

    int row0 = rowBase + ty * TM;
    int col0 = colBase + tx * TN;

    if (epi == 0) {
        const float* bi = bias + (long long)g * sBias;
        #pragma unroll
        for (int i = 0; i < TM; i++)
            #pragma unroll
            for (int j = 0; j < TN; j++)
                C[(long long)(row0 + i) * N + col0 + j] = acc[i][j] + bi[col0 + j];
    } else if (epi == 1) {
        float frx[TM], fry[TM], fcx[TN], fcy[TN];
        #pragma unroll
        for (int i = 0; i < TM; i++) { frx[i] = foot[2*(row0+i)]; fry[i] = foot[2*(row0+i)+1]; }
        #pragma unroll
        for (int j = 0; j < TN; j++) { fcx[j] = foot[2*(col0+j)]; fcy[j] = foot[2*(col0+j)+1]; }
        #pragma unroll
        for (int i = 0; i < TM; i++)
            #pragma unroll
            for (int j = 0; j < TN; j++) {
                float dx = frx[i] - fcx[j];
                float dy = fry[i] - fcy[j];
                float d2 = dx * dx + dy * dy;
                C[(long long)(row0 + i) * N + col0 + j] =
                    (d2 > THR2) ? -INFINITY : acc[i][j] * scale;
            }
    } else {
        #pragma unroll
        for (int i = 0; i < TM; i++)
            #pragma unroll
            for (int j = 0; j < TN; j++)
                C[(long long)(row0 + i) * N + col0 + j] = acc[i][j];
    }
}

// ---------------- transpose phi [g][4096][256] -> phiT [g][256][4096] ----------------
__global__ void transpose_kernel(const float* __restrict__ phi, float* __restrict__ phiT) {
    __shared__ float tile[32][33];
    int g = blockIdx.z;
    int m0 = blockIdx.x * 32;
    int r0 = blockIdx.y * 32;
    const float* src = phi  + (long long)g * NB * NFR_;
    float*       dst = phiT + (long long)g * NFR_ * NB;
    int tx = threadIdx.x, ty = threadIdx.y;  // 32 x 8
    #pragma unroll
    for (int i = ty; i < 32; i += 8)
        tile[i][tx] = src[(long long)(m0 + i) * NFR_ + r0 + tx];
    __syncthreads();
    #pragma unroll
    for (int i = ty; i < 32; i += 8)
        dst[(long long)(r0 + i) * NB + m0 + tx] = tile[tx][i];
}

// ---------------- row softmax in-place over sim [g][4096][4096] ----------------
__global__ void softmax_kernel(float* __restrict__ sim) {
    long long base = ((long long)blockIdx.y * NB + blockIdx.x) * NB;
    float* row = sim + base;
    __shared__ float red[256];
    int tid = threadIdx.x;
    float vals[16];
    float m = -INFINITY;
    #pragma unroll
    for (int i = 0; i < 16; i++) { vals[i] = row[tid + i * 256]; m = fmaxf(m, vals[i]); }
    red[tid] = m; __syncthreads();
    for (int s = 128; s > 0; s >>= 1) { if (tid < s) red[tid] = fmaxf(red[tid], red[tid + s]); __syncthreads(); }
    m = red[0]; __syncthreads();
    float sum = 0.0f;
    #pragma unroll
    for (int i = 0; i < 16; i++) { vals[i] = __expf(vals[i] - m); sum += vals[i]; }
    red[tid] = sum; __syncthreads();
    for (int s = 128; s > 0; s >>= 1) { if (tid < s) red[tid] += red[tid + s]; __syncthreads(); }
    float inv = 1.0f / red[0];
    #pragma unroll
    for (int i = 0; i < 16; i++) row[tid + i * 256] = vals[i] * inv;
}

// ---------------- final_graph = min(1, mean_g A) ----------------
__global__ void fg_kernel(const float* __restrict__ A, float* __restrict__ fg) {
    long long idx = (long long)blockIdx.x * 256 + threadIdx.x;
    const long long PER_G = (long long)NB * NB;
    if (idx < PER_G) {
        float s = 0.25f * (A[idx] + A[idx + PER_G] + A[idx + 2 * PER_G] + A[idx + 3 * PER_G]);
        fg[idx] = fminf(s, 1.0f);
    }
}

// ---------------- LayerNorm + ReLU + sum over g ----------------
__global__ void ln_kernel(const float* __restrict__ outp,
                          const float* __restrict__ gamma,
                          const float* __restrict__ beta,
                          float* __restrict__ out) {
    int n = blockIdx.x;
    int tid = threadIdx.x;  // 256
    __shared__ float red[256];
    float accum[4] = {0.f, 0.f, 0.f, 0.f};
    for (int g = 0; g < NG_; g++) {
        const float* row = outp + ((long long)g * NB + n) * NFG_;
        float v[4];
        float s = 0.0f;
        #pragma unroll
        for (int i = 0; i < 4; i++) { v[i] = row[tid + i * 256]; s += v[i]; }
        red[tid] = s; __syncthreads();
        for (int st = 128; st > 0; st >>= 1) { if (tid < st) red[tid] += red[tid + st]; __syncthreads(); }
        float mean = red[0] * (1.0f / NFG_); __syncthreads();
        float s2 = 0.0f;
        #pragma unroll
        for (int i = 0; i < 4; i++) { float d = v[i] - mean; s2 += d * d; }
        red[tid] = s2; __syncthreads();
        for (int st = 128; st > 0; st >>= 1) { if (tid < st) red[tid] += red[tid + st]; __syncthreads(); }
        float inv = rsqrtf(red[0] * (1.0f / NFG_) + 1e-5f);
        __syncthreads();
        #pragma unroll
        for (int i = 0; i < 4; i++) {
            int c = tid + i * 256;
            float y = (v[i] - mean) * inv * gamma[g * NFG_ + c] + beta[g * NFG_ + c];
            accum[i] += fmaxf(y, 0.0f);
        }
    }
    #pragma unroll
    for (int i = 0; i < 4; i++)
        out[(long long)n * NFG_ + tid + i * 256] = accum[i];
}

// ---------------- launch ----------------
extern "C" void kernel_launch(void* const* d_in, const int* in_sizes, int n_in,
                              void* d_out, int out_size) {
    const float* feats   = (const float*)d_in[0];  // [1,4096,1024]
    const float* boxes   = (const float*)d_in[1];  // [4096,4]
    const float* theta_w = (const float*)d_in[2];  // [4,1280,256]
    const float* theta_b = (const float*)d_in[3];  // [4,256]
    const float* phi_w   = (const float*)d_in[4];  // [4,1280,256]
    const float* phi_b   = (const float*)d_in[5];  // [4,256]
    const float* gcn_w   = (const float*)d_in[6];  // [4,1024,1024]
    const float* ln_g    = (const float*)d_in[7];  // [4,1024]
    const float* ln_b    = (const float*)d_in[8];  // [4,1024]
    float* out = (float*)d_out;                    // [4096*1024] out ++ [4096*4096] final_graph

    float *p_foot, *p_fpp, *p_theta, *p_phi, *p_phiT, *p_sim, *p_agg, *p_outp;
    cudaGetSymbolAddress((void**)&p_foot, g_foot);
    cudaGetSymbolAddress((void**)&p_fpp,  g_fpp);
    cudaGetSymbolAddress((void**)&p_theta, g_theta);
    cudaGetSymbolAddress((void**)&p_phi,  g_phi);
    cudaGetSymbolAddress((void**)&p_phiT, g_phiT);
    cudaGetSymbolAddress((void**)&p_sim,  g_sim);
    cudaGetSymbolAddress((void**)&p_agg,  g_agg);
    cudaGetSymbolAddress((void**)&p_outp, g_outp);

    // 1) foot points
    foot_kernel<<<(NB + 255) / 256, 256>>>(boxes, p_foot);

    // 2) fpp = [emb | feats]
    long long fppN = (long long)NB * FPPD;
    fpp_kernel<<<(unsigned)((fppN + 255) / 256), 256>>>(feats, p_foot, p_fpp);

    // 3) theta / phi: [4096,1280] @ [1280,256] + bias   (batched over g, A stride 0)
    {
        dim3 grid(NFR_ / BN, NB / BM, NG_);
        sgemm_kernel<<<grid, 256>>>(p_fpp, theta_w, p_theta, NB, NFR_, FPPD,
                                    0, (long long)FPPD * NFR_, (long long)NB * NFR_,
                                    0, theta_b, NFR_, nullptr, 0.f);
        sgemm_kernel<<<grid, 256>>>(p_fpp, phi_w, p_phi, NB, NFR_, FPPD,
                                    0, (long long)FPPD * NFR_, (long long)NB * NFR_,
                                    0, phi_b, NFR_, nullptr, 0.f);
    }

    // 4) phiT
    {
        dim3 grid(NB / 32, NFR_ / 32, NG_);
        transpose_kernel<<<grid, dim3(32, 8)>>>(p_phi, p_phiT);
    }

    // 5) sim = theta @ phiT * scale, masked
    {
        dim3 grid(NB / BN, NB / BM, NG_);
        sgemm_kernel<<<grid, 256>>>(p_theta, p_phiT, p_sim, NB, NB, NFR_,
                                    (long long)NB * NFR_, (long long)NFR_ * NB, (long long)NB * NB,
                                    1, nullptr, 0, p_foot, SIMSCALE);
    }

    // 6) softmax in place -> A
    {
        dim3 grid(NB, NG_);
        softmax_kernel<<<grid, 256>>>(p_sim);
    }

    // 7) final_graph (second output region)
    fg_kernel<<<(NB * NB) / 256, 256>>>(p_sim, out + (long long)NB * NFG_);

    // 8) agg = A @ feats : [4096,4096] @ [4096,1024]
    {
        dim3 grid(NFG_ / BN, NB / BM, NG_);
        sgemm_kernel<<<grid, 256>>>(p_sim, feats, p_agg, NB, NFG_, NB,
                                    (long long)NB * NB, 0, (long long)NB * NFG_,
                                    2, nullptr, 0, nullptr, 0.f);
    }

    // 9) outp = agg @ gcn_w : [4096,1024] @ [1024,1024]
    {
        dim3 grid(NFG_ / BN, NB / BM, NG_);
        sgemm_kernel<<<grid, 256>>>(p_agg, gcn_w, p_outp, NB, NFG_, NFG_,
                                    (long long)NB * NFG_, (long long)NFG_ * NFG_, (long long)NB * NFG_,
                                    2, nullptr, 0, nullptr, 0.f);
    }

    // 10) LN + ReLU + sum over g (first output region)
    ln_kernel<<<NB, 256>>>(p_outp, ln_g, ln_b, out);
}

// round 3
// speedup vs baseline: 1.6706x; 1.6706x over previous
#include <cuda_runtime.h>
#include <mma.h>
#include <math.h>

using namespace nvcuda;

#define NB    4096
#define NFG_  1024
#define NFP_  256
#define NFR_  256
#define NG_   4
#define FPPD  1280
#define THR2  302.76f                      // (0.2*87)^2
#define SIMSCALE 0.044194173824159216f     // 1/sqrt(512)

// ---------------- device scratch (static, allocation-free) ----------------
__device__ float g_foot[NB * 2];
__device__ float g_fpp [(size_t)NB * FPPD];
__device__ float g_theta[(size_t)NG_ * NB * NFR_];
__device__ float g_phi  [(size_t)NG_ * NB * NFR_];
__device__ float g_phiT [(size_t)NG_ * NFR_ * NB];
__device__ float g_sim  [(size_t)NG_ * NB * NB];      // becomes A in-place
__device__ float g_agg  [(size_t)NG_ * NB * NFG_];
__device__ float g_outp [(size_t)NG_ * NB * NFG_];

// ---------------- cp.async helpers ----------------
__device__ __forceinline__ void cp_async16(void* smem_dst, const void* gmem_src) {
    unsigned s = (unsigned)__cvta_generic_to_shared(smem_dst);
    asm volatile("cp.async.cg.shared.global [%0], [%1], 16;\n" :: "r"(s), "l"(gmem_src));
}
#define CP_COMMIT() asm volatile("cp.async.commit_group;\n" ::: "memory")

// ---------------- foot points ----------------
__global__ void foot_kernel(const float* __restrict__ boxes, float* __restrict__ foot) {
    int n = blockIdx.x * 256 + threadIdx.x;
    if (n < NB) {
        foot[2 * n]     = (boxes[4 * n + 0] + boxes[4 * n + 2]) * 0.5f;
        foot[2 * n + 1] = boxes[4 * n + 3];
    }
}

// ---------------- fpp = [sincos_emb(foot,256) | feats] ----------------
__global__ void fpp_kernel(const float* __restrict__ feats,
                           const float* __restrict__ foot,
                           float* __restrict__ fpp) {
    long long idx = (long long)blockIdx.x * 256 + threadIdx.x;
    if (idx >= (long long)NB * FPPD) return;
    int n = (int)(idx / FPPD);
    int j = (int)(idx % FPPD);
    float v;
    if (j < NFP_) {
        int coord = j / 128;
        int jj = j % 128;
        int i = jj & 63;
        bool is_cos = jj >= 64;
        float freq = expf(-(float)i * 0.14391157750382243f);  // 10000^(-i/64)
        float ang = foot[2 * n + coord] * freq;
        v = is_cos ? cosf(ang) : sinf(ang);
    } else {
        v = feats[(long long)n * NFG_ + (j - NFP_)];
    }
    fpp[idx] = v;
}

// ---------------- tf32 tensor-core GEMM (NN, row-major), 128x128, BK=16 ----------------
// 8 warps as 2x4; warp tile 64x32 = 4x2 wmma m16n16k8 frags.
#define GBM 128
#define GBN 128
#define GBK 16

__global__ __launch_bounds__(256, 2)
void wgemm_kernel(const float* __restrict__ Aall, const float* __restrict__ Ball,
                  float* __restrict__ Call,
                  int M, int N, int K,
                  long long sA, long long sB, long long sC)
{
    int g = blockIdx.z;
    const float* A = Aall + (long long)g * sA;
    const float* B = Ball + (long long)g * sB;
    float*       C = Call + (long long)g * sC;

    __shared__ __align__(16) float As[2][GBM][20];    // padded ldm = 20
    __shared__ __align__(16) float Bs[2][GBK][136];   // padded ldm = 136

    int tid = threadIdx.x;
    int wid = tid >> 5;
    int wr = wid >> 2;      // 0..1  -> 64-row group
    int wc = wid & 3;       // 0..3  -> 32-col group
    int rowBase = blockIdx.y * GBM;
    int colBase = blockIdx.x * GBN;

    using FragA = wmma::fragment<wmma::matrix_a, 16, 16, 8, wmma::precision::tf32, wmma::row_major>;
    using FragB = wmma::fragment<wmma::matrix_b, 16, 16, 8, wmma::precision::tf32, wmma::row_major>;
    using FragC = wmma::fragment<wmma::accumulator, 16, 16, 8, float>;

    FragC acc[4][2];
    #pragma unroll
    for (int i = 0; i < 4; i++)
        #pragma unroll
        for (int j = 0; j < 2; j++)
            wmma::fill_fragment(acc[i][j], 0.0f);

    int KT = K / GBK;

    // tile prefetch: A tile 128x16 (512 float4), B tile 16x128 (512 float4); 2 per thread each
    int fA0 = tid * 2;
    int arow0 = fA0 >> 2,  acol0 = (fA0 & 3) * 4;
    int arow1 = (fA0+1) >> 2, acol1 = ((fA0+1) & 3) * 4;
    int brow0 = fA0 >> 5,  bcol0 = (fA0 & 31) * 4;
    int brow1 = (fA0+1) >> 5, bcol1 = ((fA0+1) & 31) * 4;

    const float* Arow0 = A + (long long)(rowBase + arow0) * K;
    const float* Arow1 = A + (long long)(rowBase + arow1) * K;

    // issue tile kt into buffer buf
    #define ISSUE(kt, buf) {                                                        \
        int k0 = (kt) * GBK;                                                        \
        cp_async16(&As[buf][arow0][acol0], Arow0 + k0 + acol0);                     \
        cp_async16(&As[buf][arow1][acol1], Arow1 + k0 + acol1);                     \
        cp_async16(&Bs[buf][brow0][bcol0], B + (long long)(k0 + brow0) * N + colBase + bcol0); \
        cp_async16(&Bs[buf][brow1][bcol1], B + (long long)(k0 + brow1) * N + colBase + bcol1); \
    }

    ISSUE(0, 0); CP_COMMIT();

    for (int kt = 0; kt < KT; kt++) {
        int buf = kt & 1;
        if (kt + 1 < KT) {
            ISSUE(kt + 1, buf ^ 1); CP_COMMIT();
            asm volatile("cp.async.wait_group 1;\n" ::: "memory");
        } else {
            asm volatile("cp.async.wait_group 0;\n" ::: "memory");
        }
        __syncthreads();

        #pragma unroll
        for (int ks = 0; ks < 2; ks++) {
            FragA af[4];
            FragB bf[2];
            #pragma unroll
            for (int i = 0; i < 4; i++) {
                wmma::load_matrix_sync(af[i], &As[buf][wr * 64 + i * 16][ks * 8], 20);
                #pragma unroll
                for (int t = 0; t < af[i].num_elements; t++)
                    af[i].x[t] = wmma::__float_to_tf32(af[i].x[t]);
            }
            #pragma unroll
            for (int j = 0; j < 2; j++) {
                wmma::load_matrix_sync(bf[j], &Bs[buf][ks * 8][wc * 32 + j * 16], 136);
                #pragma unroll
                for (int t = 0; t < bf[j].num_elements; t++)
                    bf[j].x[t] = wmma::__float_to_tf32(bf[j].x[t]);
            }
            #pragma unroll
            for (int i = 0; i < 4; i++)
                #pragma unroll
                for (int j = 0; j < 2; j++)
                    wmma::mma_sync(acc[i][j], af[i], bf[j], acc[i][j]);
        }
        __syncthreads();
    }

    #pragma unroll
    for (int i = 0; i < 4; i++)
        #pragma unroll
        for (int j = 0; j < 2; j++)
            wmma::store_matrix_sync(
                C + (long long)(rowBase + wr * 64 + i * 16) * N + colBase + wc * 32 + j * 16,
                acc[i][j], N, wmma::mem_row_major);
    #undef ISSUE
}

// ---------------- in-place bias add over [4][4096][256] ----------------
__global__ void bias_kernel(float* __restrict__ x, const float* __restrict__ b) {
    int idx = blockIdx.x * 256 + threadIdx.x;           // total 4*4096*256 = 4,194,304
    int g = idx >> 20;                                  // / (NB*NFR)
    int r = idx & (NFR_ - 1);
    x[idx] += b[g * NFR_ + r];
}

// ---------------- transpose phi [g][4096][256] -> phiT [g][256][4096] ----------------
__global__ void transpose_kernel(const float* __restrict__ phi, float* __restrict__ phiT) {
    __shared__ float tile[32][33];
    int g = blockIdx.z;
    int m0 = blockIdx.x * 32;
    int r0 = blockIdx.y * 32;
    const float* src = phi  + (long long)g * NB * NFR_;
    float*       dst = phiT + (long long)g * NFR_ * NB;
    int tx = threadIdx.x, ty = threadIdx.y;  // 32 x 8
    #pragma unroll
    for (int i = ty; i < 32; i += 8)
        tile[i][tx] = src[(long long)(m0 + i) * NFR_ + r0 + tx];
    __syncthreads();
    #pragma unroll
    for (int i = ty; i < 32; i += 8)
        dst[(long long)(r0 + i) * NB + m0 + tx] = tile[tx][i];
}

// ---------------- fused scale + position-mask + row softmax (in place) ----------------
__global__ void softmax_kernel(float* __restrict__ sim, const float* __restrict__ foot) {
    int n = blockIdx.x;
    long long base = ((long long)blockIdx.y * NB + n) * NB;
    float* row = sim + base;
    __shared__ float red[256];
    int tid = threadIdx.x;
    float frx = foot[2 * n], fry = foot[2 * n + 1];

    float vals[16];
    float m = -INFINITY;
    #pragma unroll
    for (int i = 0; i < 16; i++) {
        int c = tid + i * 256;
        float dx = frx - foot[2 * c];
        float dy = fry - foot[2 * c + 1];
        float d2 = dx * dx + dy * dy;
        float s = row[c];
        vals[i] = (d2 > THR2) ? -INFINITY : s * SIMSCALE;
        m = fmaxf(m, vals[i]);
    }
    red[tid] = m; __syncthreads();
    for (int s = 128; s > 0; s >>= 1) { if (tid < s) red[tid] = fmaxf(red[tid], red[tid + s]); __syncthreads(); }
    m = red[0]; __syncthreads();
    float sum = 0.0f;
    #pragma unroll
    for (int i = 0; i < 16; i++) { vals[i] = __expf(vals[i] - m); sum += vals[i]; }
    red[tid] = sum; __syncthreads();
    for (int s = 128; s > 0; s >>= 1) { if (tid < s) red[tid] += red[tid + s]; __syncthreads(); }
    float inv = 1.0f / red[0];
    #pragma unroll
    for (int i = 0; i < 16; i++) row[tid + i * 256] = vals[i] * inv;
}

// ---------------- final_graph = min(1, mean_g A) ----------------
__global__ void fg_kernel(const float* __restrict__ A, float* __restrict__ fg) {
    long long idx = (long long)blockIdx.x * 256 + threadIdx.x;
    const long long PER_G = (long long)NB * NB;
    if (idx < PER_G) {
        float s = 0.25f * (A[idx] + A[idx + PER_G] + A[idx + 2 * PER_G] + A[idx + 3 * PER_G]);
        fg[idx] = fminf(s, 1.0f);
    }
}

// ---------------- LayerNorm + ReLU + sum over g ----------------
__global__ void ln_kernel(const float* __restrict__ outp,
                          const float* __restrict__ gamma,
                          const float* __restrict__ beta,
                          float* __restrict__ out) {
    int n = blockIdx.x;
    int tid = threadIdx.x;  // 256
    __shared__ float red[256];
    float accum[4] = {0.f, 0.f, 0.f, 0.f};
    for (int g = 0; g < NG_; g++) {
        const float* row = outp + ((long long)g * NB + n) * NFG_;
        float v[4];
        float s = 0.0f;
        #pragma unroll
        for (int i = 0; i < 4; i++) { v[i] = row[tid + i * 256]; s += v[i]; }
        red[tid] = s; __syncthreads();
        for (int st = 128; st > 0; st >>= 1) { if (tid < st) red[tid] += red[tid + st]; __syncthreads(); }
        float mean = red[0] * (1.0f / NFG_); __syncthreads();
        float s2 = 0.0f;
        #pragma unroll
        for (int i = 0; i < 4; i++) { float d = v[i] - mean; s2 += d * d; }
        red[tid] = s2; __syncthreads();
        for (int st = 128; st > 0; st >>= 1) { if (tid < st) red[tid] += red[tid + st]; __syncthreads(); }
        float inv = rsqrtf(red[0] * (1.0f / NFG_) + 1e-5f);
        __syncthreads();
        #pragma unroll
        for (int i = 0; i < 4; i++) {
            int c = tid + i * 256;
            float y = (v[i] - mean) * inv * gamma[g * NFG_ + c] + beta[g * NFG_ + c];
            accum[i] += fmaxf(y, 0.0f);
        }
    }
    #pragma unroll
    for (int i = 0; i < 4; i++)
        out[(long long)n * NFG_ + tid + i * 256] = accum[i];
}

// ---------------- launch ----------------
extern "C" void kernel_launch(void* const* d_in, const int* in_sizes, int n_in,
                              void* d_out, int out_size) {
    const float* feats   = (const float*)d_in[0];
    const float* boxes   = (const float*)d_in[1];
    const float* theta_w = (const float*)d_in[2];
    const float* theta_b = (const float*)d_in[3];
    const float* phi_w   = (const float*)d_in[4];
    const float* phi_b   = (const float*)d_in[5];
    const float* gcn_w   = (const float*)d_in[6];
    const float* ln_g    = (const float*)d_in[7];
    const float* ln_b    = (const float*)d_in[8];
    float* out = (float*)d_out;   // [4096*1024] out ++ [4096*4096] final_graph

    float *p_foot, *p_fpp, *p_theta, *p_phi, *p_phiT, *p_sim, *p_agg, *p_outp;
    cudaGetSymbolAddress((void**)&p_foot, g_foot);
    cudaGetSymbolAddress((void**)&p_fpp,  g_fpp);
    cudaGetSymbolAddress((void**)&p_theta, g_theta);
    cudaGetSymbolAddress((void**)&p_phi,  g_phi);
    cudaGetSymbolAddress((void**)&p_phiT, g_phiT);
    cudaGetSymbolAddress((void**)&p_sim,  g_sim);
    cudaGetSymbolAddress((void**)&p_agg,  g_agg);
    cudaGetSymbolAddress((void**)&p_outp, g_outp);

    // 1) foot points
    foot_kernel<<<(NB + 255) / 256, 256>>>(boxes, p_foot);

    // 2) fpp
    long long fppN = (long long)NB * FPPD;
    fpp_kernel<<<(unsigned)((fppN + 255) / 256), 256>>>(feats, p_foot, p_fpp);

    // 3) theta / phi GEMMs (tf32 tensor cores), then bias
    {
        dim3 grid(NFR_ / GBN, NB / GBM, NG_);
        wgemm_kernel<<<grid, 256>>>(p_fpp, theta_w, p_theta, NB, NFR_, FPPD,
                                    0, (long long)FPPD * NFR_, (long long)NB * NFR_);
        wgemm_kernel<<<grid, 256>>>(p_fpp, phi_w, p_phi, NB, NFR_, FPPD,
                                    0, (long long)FPPD * NFR_, (long long)NB * NFR_);
        int nb = NG_ * NB * NFR_ / 256;
        bias_kernel<<<nb, 256>>>(p_theta, theta_b);
        bias_kernel<<<nb, 256>>>(p_phi, phi_b);
    }

    // 4) phiT
    {
        dim3 grid(NB / 32, NFR_ / 32, NG_);
        transpose_kernel<<<grid, dim3(32, 8)>>>(p_phi, p_phiT);
    }

    // 5) sim = theta @ phiT  (scale+mask folded into softmax)
    {
        dim3 grid(NB / GBN, NB / GBM, NG_);
        wgemm_kernel<<<grid, 256>>>(p_theta, p_phiT, p_sim, NB, NB, NFR_,
                                    (long long)NB * NFR_, (long long)NFR_ * NB, (long long)NB * NB);
    }

    // 6) softmax (fused scale + position mask) -> A in place
    {
        dim3 grid(NB, NG_);
        softmax_kernel<<<grid, 256>>>(p_sim, p_foot);
    }

    // 7) final_graph
    fg_kernel<<<(NB * NB) / 256, 256>>>(p_sim, out + (long long)NB * NFG_);

    // 8) agg = A @ feats
    {
        dim3 grid(NFG_ / GBN, NB / GBM, NG_);
        wgemm_kernel<<<grid, 256>>>(p_sim, feats, p_agg, NB, NFG_, NB,
                                    (long long)NB * NB, 0, (long long)NB * NFG_);
    }

    // 9) outp = agg @ gcn_w
    {
        dim3 grid(NFG_ / GBN, NB / GBM, NG_);
        wgemm_kernel<<<grid, 256>>>(p_agg, gcn_w, p_outp, NB, NFG_, NFG_,
                                    (long long)NB * NFG_, (long long)NFG_ * NFG_, (long long)NB * NFG_);
    }

    // 10) LN + ReLU + sum over g
    ln_kernel<<<NB, 256>>>(p_outp, ln_g, ln_b, out);
}

// round 5
// speedup vs baseline: 5.5599x; 3.3281x over previous
#include <cuda_runtime.h>
#include <cuda_fp16.h>
#include <mma.h>
#include <math.h>
#include <stdint.h>

using namespace nvcuda;

#define NB    4096
#define NFG_  1024
#define NFP_  256
#define NFR_  256
#define NG_   4
#define FPPD  1280
#define THR2  302.76f                      // (0.2*87)^2
#define SIMSCALE 0.044194173824159216f     // 1/sqrt(512)

// ---------------- device scratch (static, allocation-free) ----------------
__device__ float  g_foot[NB * 2];
__device__ __half g_fpp_h [(size_t)NB * FPPD];            // A of theta/phi
__device__ __half g_thW_h [(size_t)NG_ * FPPD * NFR_];    // theta_w fp16 (row-major K x N)
__device__ __half g_phW_h [(size_t)NG_ * FPPD * NFR_];
__device__ __half g_gwW_h [(size_t)NG_ * NFG_ * NFG_];    // gcn_w fp16
__device__ __half g_ft_h  [(size_t)NB * NFG_];            // feats fp16
__device__ float  g_thphi [(size_t)2 * NG_ * NB * NFR_];  // theta|phi fp32 (pre-bias)
__device__ __half g_theta_h[(size_t)NG_ * NB * NFR_];
__device__ __half g_phi_h  [(size_t)NG_ * NB * NFR_];
__device__ float  g_sim  [(size_t)NG_ * NB * NB];         // 256 MB
__device__ __half g_A_h  [(size_t)NG_ * NB * NB];         // 128 MB
__device__ float  g_aggf [(size_t)NG_ * NB * NFG_];       // 64 MB
__device__ __half g_agg_h[(size_t)NG_ * NB * NFG_];       // 32 MB
__device__ float  g_outp [(size_t)NG_ * NB * NFG_];       // 64 MB

// ---------------- cp.async helpers ----------------
__device__ __forceinline__ void cp_async16(void* smem_dst, const void* gmem_src) {
    unsigned s = (unsigned)__cvta_generic_to_shared(smem_dst);
    asm volatile("cp.async.cg.shared.global [%0], [%1], 16;\n" :: "r"(s), "l"(gmem_src));
}
#define CP_COMMIT() asm volatile("cp.async.commit_group;\n" ::: "memory")

// ---------------- foot points ----------------
__global__ void foot_kernel(const float* __restrict__ boxes, float* __restrict__ foot) {
    int n = blockIdx.x * 256 + threadIdx.x;
    if (n < NB) {
        foot[2 * n]     = (boxes[4 * n + 0] + boxes[4 * n + 2]) * 0.5f;
        foot[2 * n + 1] = boxes[4 * n + 3];
    }
}

// ---------------- fpp (fp16) = [sincos_emb(foot,256) | feats] ----------------
__global__ void fpp_kernel(const float* __restrict__ feats,
                           const float* __restrict__ foot,
                           __half* __restrict__ fpp) {
    long long idx = (long long)blockIdx.x * 256 + threadIdx.x;
    if (idx >= (long long)NB * FPPD) return;
    int n = (int)(idx / FPPD);
    int j = (int)(idx % FPPD);
    float v;
    if (j < NFP_) {
        int coord = j / 128;
        int jj = j % 128;
        int i = jj & 63;
        bool is_cos = jj >= 64;
        float freq = expf(-(float)i * 0.14391157750382243f);  // 10000^(-i/64)
        float ang = foot[2 * n + coord] * freq;
        v = is_cos ? cosf(ang) : sinf(ang);
    } else {
        v = feats[(long long)n * NFG_ + (j - NFP_)];
    }
    fpp[idx] = __float2half(v);
}

// ---------------- elementwise fp32 -> fp16 ----------------
__global__ void conv_kernel(const float* __restrict__ in, __half* __restrict__ out, long long n) {
    long long i = ((long long)blockIdx.x * 256 + threadIdx.x) * 4;
    if (i >= n) return;
    float4 v = *(const float4*)(in + i);
    __half2 h0 = __floats2half2_rn(v.x, v.y);
    __half2 h1 = __floats2half2_rn(v.z, v.w);
    *(uint2*)(out + i) = make_uint2(*(uint32_t*)&h0, *(uint32_t*)&h1);
}

// ---------------- bias + convert for theta/phi [g][4096][256] ----------------
__global__ void biasconv_kernel(const float* __restrict__ x, const float* __restrict__ b,
                                __half* __restrict__ out) {
    int idx = (blockIdx.x * 256 + threadIdx.x) * 2;          // over 4*4096*256
    int g = idx >> 20;
    int r = idx & (NFR_ - 1);
    float2 v = *(const float2*)(x + idx);
    float2 bb = *(const float2*)(b + g * NFR_ + r);
    __half2 h = __floats2half2_rn(v.x + bb.x, v.y + bb.y);
    *(uint32_t*)(out + idx) = *(uint32_t*)&h;
}

// ======================= fp16 wmma GEMM, 128x128, BK=32 =======================
// C[M,N] fp32 = A[M,K](fp16 row-major) @ B
//   TRANSB=0: B is [K,N] fp16 row-major
//   TRANSB=1: B is [N,K] fp16 row-major (i.e. computes A @ B^T)
#define GBM 128
#define GBN 128
#define GBK 32
#define APAD 40     // halves per A row (32 + 8)
#define BPAD 136    // halves per B row, nontrans (128 + 8)

template<int TRANSB>
__global__ __launch_bounds__(256, 2)
void hgemm_kernel(const __half* __restrict__ Aall, const __half* __restrict__ Ball,
                  float* __restrict__ Call,
                  int M, int N, int K,
                  long long sA, long long sB, long long sC)
{
    int g = blockIdx.z;
    const __half* A = Aall + (long long)g * sA;
    const __half* B = Ball + (long long)g * sB;
    float*        C = Call + (long long)g * sC;

    __shared__ __align__(16) __half As[2][GBM][APAD];
    __shared__ __align__(16) __half Bs[2][TRANSB ? GBN * APAD : GBK * BPAD];

    int tid = threadIdx.x;
    int wid = tid >> 5;
    int wr = wid >> 2;      // 0..1  -> 64-row group
    int wc = wid & 3;       // 0..3  -> 32-col group
    int rowBase = blockIdx.y * GBM;
    int colBase = blockIdx.x * GBN;

    using FragA = wmma::fragment<wmma::matrix_a, 16, 16, 16, __half, wmma::row_major>;
    using FragBr = wmma::fragment<wmma::matrix_b, 16, 16, 16, __half, wmma::row_major>;
    using FragBc = wmma::fragment<wmma::matrix_b, 16, 16, 16, __half, wmma::col_major>;
    using FragC = wmma::fragment<wmma::accumulator, 16, 16, 16, float>;

    FragC acc[4][2];
    #pragma unroll
    for (int i = 0; i < 4; i++)
        #pragma unroll
        for (int j = 0; j < 2; j++)
            wmma::fill_fragment(acc[i][j], 0.0f);

    int KT = K / GBK;

    // A tile: 128 rows x 32 halves = 512 x 16B units; 2 units/thread
    // B tile: same byte count
    int u0 = tid * 2;

    #define ISSUE(kt, buf) {                                                              \
        int k0 = (kt) * GBK;                                                              \
        _Pragma("unroll")                                                                 \
        for (int q = 0; q < 2; q++) {                                                     \
            int u = u0 + q;                                                               \
            int ar = u >> 2, ac = (u & 3) * 8;                                            \
            cp_async16(&As[buf][ar][ac], A + (long long)(rowBase + ar) * K + k0 + ac);    \
            if (TRANSB) {                                                                 \
                int br = u >> 2, bc = (u & 3) * 8;                                        \
                cp_async16(&Bs[buf][br * APAD + bc],                                      \
                           B + (long long)(colBase + br) * K + k0 + bc);                  \
            } else {                                                                      \
                int br = u >> 4, bc = (u & 15) * 8;                                       \
                cp_async16(&Bs[buf][br * BPAD + bc],                                      \
                           B + (long long)(k0 + br) * N + colBase + bc);                  \
            }                                                                             \
        }                                                                                 \
    }

    ISSUE(0, 0); CP_COMMIT();

    for (int kt = 0; kt < KT; kt++) {
        int buf = kt & 1;
        if (kt + 1 < KT) {
            ISSUE(kt + 1, buf ^ 1); CP_COMMIT();
            asm volatile("cp.async.wait_group 1;\n" ::: "memory");
        } else {
            asm volatile("cp.async.wait_group 0;\n" ::: "memory");
        }
        __syncthreads();

        #pragma unroll
        for (int ks = 0; ks < 2; ks++) {
            FragA af[4];
            #pragma unroll
            for (int i = 0; i < 4; i++)
                wmma::load_matrix_sync(af[i], &As[buf][wr * 64 + i * 16][ks * 16], APAD);
            if (TRANSB) {
                FragBc bf[2];
                #pragma unroll
                for (int j = 0; j < 2; j++)
                    wmma::load_matrix_sync(bf[j], &Bs[buf][(wc * 32 + j * 16) * APAD + ks * 16], APAD);
                #pragma unroll
                for (int i = 0; i < 4; i++)
                    #pragma unroll
                    for (int j = 0; j < 2; j++)
                        wmma::mma_sync(acc[i][j], af[i], bf[j], acc[i][j]);
            } else {
                FragBr bf[2];
                #pragma unroll
                for (int j = 0; j < 2; j++)
                    wmma::load_matrix_sync(bf[j], &Bs[buf][(ks * 16) * BPAD + wc * 32 + j * 16], BPAD);
                #pragma unroll
                for (int i = 0; i < 4; i++)
                    #pragma unroll
                    for (int j = 0; j < 2; j++)
                        wmma::mma_sync(acc[i][j], af[i], bf[j], acc[i][j]);
            }
        }
        __syncthreads();
    }

    #pragma unroll
    for (int i = 0; i < 4; i++)
        #pragma unroll
        for (int j = 0; j < 2; j++)
            wmma::store_matrix_sync(
                C + (long long)(rowBase + wr * 64 + i * 16) * N + colBase + wc * 32 + j * 16,
                acc[i][j], N, wmma::mem_row_major);
    #undef ISSUE
}

// ---------------- fused scale + position-mask + row softmax: fp32 -> fp16 ----------------
__global__ void softmax_kernel(const float* __restrict__ sim, __half* __restrict__ Ah,
                               const float* __restrict__ foot) {
    int n = blockIdx.x;
    long long base = ((long long)blockIdx.y * NB + n) * NB;
    const float* row = sim + base;
    __half* orow = Ah + base;
    __shared__ float red[256];
    int tid = threadIdx.x;
    float frx = foot[2 * n], fry = foot[2 * n + 1];

    float vals[16];
    float m = -INFINITY;
    #pragma unroll
    for (int i = 0; i < 16; i++) {
        int c = tid + i * 256;
        float dx = frx - foot[2 * c];
        float dy = fry - foot[2 * c + 1];
        float d2 = dx * dx + dy * dy;
        float s = row[c];
        vals[i] = (d2 > THR2) ? -INFINITY : s * SIMSCALE;
        m = fmaxf(m, vals[i]);
    }
    red[tid] = m; __syncthreads();
    for (int s = 128; s > 0; s >>= 1) { if (tid < s) red[tid] = fmaxf(red[tid], red[tid + s]); __syncthreads(); }
    m = red[0]; __syncthreads();
    float sum = 0.0f;
    #pragma unroll
    for (int i = 0; i < 16; i++) { vals[i] = __expf(vals[i] - m); sum += vals[i]; }
    red[tid] = sum; __syncthreads();
    for (int s = 128; s > 0; s >>= 1) { if (tid < s) red[tid] += red[tid + s]; __syncthreads(); }
    float inv = 1.0f / red[0];
    #pragma unroll
    for (int i = 0; i < 16; i++) orow[tid + i * 256] = __float2half(vals[i] * inv);
}

// ---------------- final_graph = min(1, mean_g A) ----------------
__global__ void fg_kernel(const __half* __restrict__ Ah, float* __restrict__ fg) {
    long long idx = (long long)blockIdx.x * 256 + threadIdx.x;
    const long long PER_G = (long long)NB * NB;
    if (idx < PER_G) {
        float s = 0.25f * (__half2float(Ah[idx]) + __half2float(Ah[idx + PER_G]) +
                           __half2float(Ah[idx + 2 * PER_G]) + __half2float(Ah[idx + 3 * PER_G]));
        fg[idx] = fminf(s, 1.0f);
    }
}

// ---------------- LayerNorm + ReLU + sum over g ----------------
__global__ void ln_kernel(const float* __restrict__ outp,
                          const float* __restrict__ gamma,
                          const float* __restrict__ beta,
                          float* __restrict__ out) {
    int n = blockIdx.x;
    int tid = threadIdx.x;  // 256
    __shared__ float red[256];
    float accum[4] = {0.f, 0.f, 0.f, 0.f};
    for (int g = 0; g < NG_; g++) {
        const float* row = outp + ((long long)g * NB + n) * NFG_;
        float v[4];
        float s = 0.0f;
        #pragma unroll
        for (int i = 0; i < 4; i++) { v[i] = row[tid + i * 256]; s += v[i]; }
        red[tid] = s; __syncthreads();
        for (int st = 128; st > 0; st >>= 1) { if (tid < st) red[tid] += red[tid + st]; __syncthreads(); }
        float mean = red[0] * (1.0f / NFG_); __syncthreads();
        float s2 = 0.0f;
        #pragma unroll
        for (int i = 0; i < 4; i++) { float d = v[i] - mean; s2 += d * d; }
        red[tid] = s2; __syncthreads();
        for (int st = 128; st > 0; st >>= 1) { if (tid < st) red[tid] += red[tid + st]; __syncthreads(); }
        float inv = rsqrtf(red[0] * (1.0f / NFG_) + 1e-5f);
        __syncthreads();
        #pragma unroll
        for (int i = 0; i < 4; i++) {
            int c = tid + i * 256;
            float y = (v[i] - mean) * inv * gamma[g * NFG_ + c] + beta[g * NFG_ + c];
            accum[i] += fmaxf(y, 0.0f);
        }
    }
    #pragma unroll
    for (int i = 0; i < 4; i++)
        out[(long long)n * NFG_ + tid + i * 256] = accum[i];
}

// ======================= launch =======================
extern "C" void kernel_launch(void* const* d_in, const int* in_sizes, int n_in,
                              void* d_out, int out_size) {
    const float* feats   = (const float*)d_in[0];
    const float* boxes   = (const float*)d_in[1];
    const float* theta_w = (const float*)d_in[2];
    const float* theta_b = (const float*)d_in[3];
    const float* phi_w   = (const float*)d_in[4];
    const float* phi_b   = (const float*)d_in[5];
    const float* gcn_w   = (const float*)d_in[6];
    const float* ln_g    = (const float*)d_in[7];
    const float* ln_b    = (const float*)d_in[8];
    float* out = (float*)d_out;   // [4096*1024] out ++ [4096*4096] final_graph

    float *p_foot, *p_thphi, *p_sim, *p_aggf, *p_outp;
    __half *p_fpp, *p_thW, *p_phW, *p_gwW, *p_ft, *p_theta, *p_phi, *p_Ah, *p_agg;
    cudaGetSymbolAddress((void**)&p_foot, g_foot);
    cudaGetSymbolAddress((void**)&p_fpp,  g_fpp_h);
    cudaGetSymbolAddress((void**)&p_thW,  g_thW_h);
    cudaGetSymbolAddress((void**)&p_phW,  g_phW_h);
    cudaGetSymbolAddress((void**)&p_gwW,  g_gwW_h);
    cudaGetSymbolAddress((void**)&p_ft,   g_ft_h);
    cudaGetSymbolAddress((void**)&p_thphi, g_thphi);
    cudaGetSymbolAddress((void**)&p_theta, g_theta_h);
    cudaGetSymbolAddress((void**)&p_phi,  g_phi_h);
    cudaGetSymbolAddress((void**)&p_sim,  g_sim);
    cudaGetSymbolAddress((void**)&p_Ah,   g_A_h);
    cudaGetSymbolAddress((void**)&p_aggf, g_aggf);
    cudaGetSymbolAddress((void**)&p_agg,  g_agg_h);
    cudaGetSymbolAddress((void**)&p_outp, g_outp);

    float* p_thetaF = p_thphi;
    float* p_phiF   = p_thphi + (size_t)NG_ * NB * NFR_;

    // 1) foot + fpp(fp16)
    foot_kernel<<<(NB + 255) / 256, 256>>>(boxes, p_foot);
    long long fppN = (long long)NB * FPPD;
    fpp_kernel<<<(unsigned)((fppN + 255) / 256), 256>>>(feats, p_foot, p_fpp);

    // 2) fp16 operand conversions (elementwise, no transposes)
    {
        long long nw = (long long)NG_ * FPPD * NFR_;
        conv_kernel<<<(unsigned)(nw / 4 / 256), 256>>>(theta_w, p_thW, nw);
        conv_kernel<<<(unsigned)(nw / 4 / 256), 256>>>(phi_w, p_phW, nw);
        long long ng = (long long)NG_ * NFG_ * NFG_;
        conv_kernel<<<(unsigned)(ng / 4 / 256), 256>>>(gcn_w, p_gwW, ng);
        long long nf = (long long)NB * NFG_;
        conv_kernel<<<(unsigned)(nf / 4 / 256), 256>>>(feats, p_ft, nf);
    }

    // 3) theta/phi GEMMs: [4096,1280] @ [1280,256] (fp32 out), then bias+fp16
    {
        dim3 grid(NFR_ / GBN, NB / GBM, NG_);
        hgemm_kernel<0><<<grid, 256>>>(p_fpp, p_thW, p_thetaF, NB, NFR_, FPPD,
                                       0, (long long)FPPD * NFR_, (long long)NB * NFR_);
        hgemm_kernel<0><<<grid, 256>>>(p_fpp, p_phW, p_phiF, NB, NFR_, FPPD,
                                       0, (long long)FPPD * NFR_, (long long)NB * NFR_);
        int nb = NG_ * NB * NFR_ / 2 / 256;
        biasconv_kernel<<<nb, 256>>>(p_thetaF, theta_b, p_theta);
        biasconv_kernel<<<nb, 256>>>(p_phiF, phi_b, p_phi);
    }

    // 4) sim = theta @ phi^T (TRANSB; phi row-major [N,K] read as col-major B)
    {
        dim3 grid(NB / GBN, NB / GBM, NG_);
        hgemm_kernel<1><<<grid, 256>>>(p_theta, p_phi, p_sim, NB, NB, NFR_,
                                       (long long)NB * NFR_, (long long)NB * NFR_,
                                       (long long)NB * NB);
    }

    // 5) softmax (scale + mask fused) -> fp16 A
    softmax_kernel<<<dim3(NB, NG_), 256>>>(p_sim, p_Ah, p_foot);

    // 6) final_graph
    fg_kernel<<<(NB * NB) / 256, 256>>>(p_Ah, out + (long long)NB * NFG_);

    // 7) agg = A @ feats (fp32 out), convert to fp16
    {
        dim3 grid(NFG_ / GBN, NB / GBM, NG_);
        hgemm_kernel<0><<<grid, 256>>>(p_Ah, p_ft, p_aggf, NB, NFG_, NB,
                                       (long long)NB * NB, 0, (long long)NB * NFG_);
        long long na = (long long)NG_ * NB * NFG_;
        conv_kernel<<<(unsigned)(na / 4 / 256), 256>>>(p_aggf, p_agg, na);
    }

    // 8) outp = agg @ gcn_w (fp32 out)
    {
        dim3 grid(NFG_ / GBN, NB / GBM, NG_);
        hgemm_kernel<0><<<grid, 256>>>(p_agg, p_gwW, p_outp, NB, NFG_, NFG_,
                                       (long long)NB * NFG_, (long long)NFG_ * NFG_,
                                       (long long)NB * NFG_);
    }

    // 9) LN + ReLU + sum over g
    ln_kernel<<<NB, 256>>>(p_outp, ln_g, ln_b, out);
}